// round 4
// baseline (speedup 1.0000x reference)
#include <cuda_runtime.h>
#include <math_constants.h>
#include <cstdint>
#include <cstddef>

#define BATCH 2
#define NPT   4096
#define NB    (BATCH * NPT)
#define KNN   20
#define SPAD  36   // smem row stride in words (bank-conflict-free for frag loads)

// ---------------- scratch (device globals; no allocation) ----------------
__device__ float    g_dist[(size_t)NB * NPT];    // 134 MB distance matrix (reused per layer)
__device__ int      g_idx[NB * KNN];
__device__ float    g_xx[NB];
__device__ float    g_xcat[(size_t)NB * 512];    // x1|x2|x3|x4 at offsets 0/64/128/256
__device__ float    g_base[(size_t)NB * 256];
__device__ float    g_Wc[256 * 128];
__device__ uint32_t g_Xh[(size_t)NB * 512];      // tf32 hi split (activations, packed)
__device__ uint32_t g_Xl[(size_t)NB * 512];      // tf32 lo split
__device__ uint32_t g_Wh[1024 * 512];            // tf32 hi split (weights, packed)
__device__ uint32_t g_Wl[1024 * 512];
__device__ float    g_act[(size_t)NB * 1024];
__device__ float    g_gvec[BATCH * 1024];
__device__ float    g_sterm[BATCH * 512];
__device__ float    g_h1[(size_t)NB * 512];
__device__ float    g_h2[(size_t)NB * 256];

// ---------------- tf32 helpers ----------------
__device__ __forceinline__ uint32_t f2tf(float f) {
    uint32_t u; asm("cvt.rna.tf32.f32 %0, %1;" : "=r"(u) : "f"(f)); return u;
}
__device__ __forceinline__ void mma8(float* c, const uint32_t* a, const uint32_t* b) {
    asm volatile("mma.sync.aligned.m16n8k8.row.col.f32.tf32.tf32.f32 "
        "{%0,%1,%2,%3}, {%4,%5,%6,%7}, {%8,%9}, {%0,%1,%2,%3};"
        : "+f"(c[0]), "+f"(c[1]), "+f"(c[2]), "+f"(c[3])
        : "r"(a[0]), "r"(a[1]), "r"(a[2]), "r"(a[3]), "r"(b[0]), "r"(b[1]));
}

// ---------------- split fp32 -> tf32 hi/lo (strided in, packed out) ----------------
__global__ void k_split(const float* __restrict__ in, int rows, int cols, int rsIn,
                        uint32_t* __restrict__ hi, uint32_t* __restrict__ lo) {
    int total = rows * cols;
    for (int i = blockIdx.x * blockDim.x + threadIdx.x; i < total;
         i += gridDim.x * blockDim.x) {
        int r = i / cols, c = i - r * cols;
        float v = in[(size_t)r * rsIn + c];
        uint32_t h = f2tf(v);
        hi[i] = h;
        lo[i] = f2tf(v - __uint_as_float(h));
    }
}

// ---------------- squared norms ----------------
__global__ void k_sqnorm(const float* __restrict__ X, int rs, int C, float* __restrict__ xx) {
    int i = blockIdx.x * blockDim.x + threadIdx.x;
    if (i >= NB) return;
    const float* r = X + (size_t)i * rs;
    float s = 0.f;
    for (int c = 0; c < C; c++) s = fmaf(r[c], r[c], s);
    xx[i] = s;
}

// ---------------- scalar pairwise distance (layer 1, C=3 only) ----------------
__global__ void k_dist3(const float* __restrict__ X,
                        const float* __restrict__ xx, float* __restrict__ D) {
    int bi = blockIdx.x * 64;
    int bj = blockIdx.y * 64;
    int b  = blockIdx.z;
    const float* Xb  = X  + (size_t)b * NPT * 3;
    const float* xxb = xx + b * NPT;
    __shared__ float sA[64][3];
    __shared__ float sB[64][3];
    int t = threadIdx.x;
    if (t < 64) {
        sA[t][0] = Xb[(bi + t) * 3 + 0];
        sA[t][1] = Xb[(bi + t) * 3 + 1];
        sA[t][2] = Xb[(bi + t) * 3 + 2];
    } else {
        int u = t - 64;
        sB[u][0] = Xb[(bj + u) * 3 + 0];
        sB[u][1] = Xb[(bj + u) * 3 + 1];
        sB[u][2] = Xb[(bj + u) * 3 + 2];
    }
    __syncthreads();
    int mi = t & 7, oj = t >> 3;
#pragma unroll
    for (int ri = 0; ri < 8; ri++) {
        int i = mi * 8 + ri;
        float a0 = sA[i][0], a1 = sA[i][1], a2 = sA[i][2];
        float xi = xxb[bi + i];
        float4 v;
        int j0 = oj * 4;
        float* vv = &v.x;
#pragma unroll
        for (int c = 0; c < 4; c++) {
            int j = j0 + c;
            float dp = a0 * sB[j][0] + a1 * sB[j][1] + a2 * sB[j][2];
            vv[c] = xi + xxb[bj + j] - 2.f * dp;
        }
        *(float4*)(D + ((size_t)b * NPT + bi + i) * NPT + bj + j0) = v;
    }
}

// ---------------- 3xtf32 mma pairwise distance (pre-split X, packed [NB x C]) -----------
// grid (NPT/64, NPT/64, B), block 128 (4 warps); warp tile 32x32
__global__ void k_dist_mma(const uint32_t* __restrict__ Xh, const uint32_t* __restrict__ Xl,
                           int C, const float* __restrict__ xx, float* __restrict__ D) {
    int m0 = blockIdx.x * 64;
    int n0 = blockIdx.y * 64;
    int b  = blockIdx.z;
    const uint32_t* Xbh = Xh + (size_t)b * NPT * C;
    const uint32_t* Xbl = Xl + (size_t)b * NPT * C;
    const float* xxb = xx + b * NPT;
    __shared__ uint32_t sAh[64 * SPAD];
    __shared__ uint32_t sAl[64 * SPAD];
    __shared__ uint32_t sBh[64 * SPAD];
    __shared__ uint32_t sBl[64 * SPAD];
    int t = threadIdx.x;
    int warp = t >> 5, lane = t & 31;
    int g = lane >> 2, tg = lane & 3;
    int wm = (warp & 1) * 32, wn = (warp >> 1) * 32;
    float acc[2][4][4] = {};
    int lr = t >> 3, lc = (t & 7) * 4;
    for (int k0 = 0; k0 < C; k0 += 32) {
#pragma unroll
        for (int rr = 0; rr < 64; rr += 16) {
            *(uint4*)&sAh[(lr + rr) * SPAD + lc] =
                *(const uint4*)(Xbh + (size_t)(m0 + lr + rr) * C + k0 + lc);
            *(uint4*)&sAl[(lr + rr) * SPAD + lc] =
                *(const uint4*)(Xbl + (size_t)(m0 + lr + rr) * C + k0 + lc);
            *(uint4*)&sBh[(lr + rr) * SPAD + lc] =
                *(const uint4*)(Xbh + (size_t)(n0 + lr + rr) * C + k0 + lc);
            *(uint4*)&sBl[(lr + rr) * SPAD + lc] =
                *(const uint4*)(Xbl + (size_t)(n0 + lr + rr) * C + k0 + lc);
        }
        __syncthreads();
#pragma unroll
        for (int kk = 0; kk < 32; kk += 8) {
            uint32_t afh[2][4], afl[2][4], bfh[4][2], bfl[4][2];
#pragma unroll
            for (int mt = 0; mt < 2; mt++) {
                int r0 = (wm + mt * 16 + g) * SPAD + kk + tg;
                int r1 = (wm + mt * 16 + g + 8) * SPAD + kk + tg;
                afh[mt][0] = sAh[r0]; afh[mt][1] = sAh[r1];
                afh[mt][2] = sAh[r0 + 4]; afh[mt][3] = sAh[r1 + 4];
                afl[mt][0] = sAl[r0]; afl[mt][1] = sAl[r1];
                afl[mt][2] = sAl[r0 + 4]; afl[mt][3] = sAl[r1 + 4];
            }
#pragma unroll
            for (int nt = 0; nt < 4; nt++) {
                int r0 = (wn + nt * 8 + g) * SPAD + kk + tg;
                bfh[nt][0] = sBh[r0]; bfh[nt][1] = sBh[r0 + 4];
                bfl[nt][0] = sBl[r0]; bfl[nt][1] = sBl[r0 + 4];
            }
#pragma unroll
            for (int mt = 0; mt < 2; mt++)
#pragma unroll
                for (int nt = 0; nt < 4; nt++) {
                    mma8(acc[mt][nt], afh[mt], bfl[nt]);
                    mma8(acc[mt][nt], afl[mt], bfh[nt]);
                    mma8(acc[mt][nt], afh[mt], bfh[nt]);
                }
        }
        __syncthreads();
    }
#pragma unroll
    for (int mt = 0; mt < 2; mt++)
#pragma unroll
        for (int rh = 0; rh < 2; rh++) {
            int i = m0 + wm + mt * 16 + g + rh * 8;
            float xi = xxb[i];
#pragma unroll
            for (int nt = 0; nt < 4; nt++) {
                int j = n0 + wn + nt * 8 + tg * 2;
                float v0 = xi + xxb[j]     - 2.f * acc[mt][nt][rh * 2 + 0];
                float v1 = xi + xxb[j + 1] - 2.f * acc[mt][nt][rh * 2 + 1];
                *(float2*)(D + ((size_t)b * NPT + i) * NPT + j) = make_float2(v0, v1);
            }
        }
}

// ---------------- warp-per-row top-20 smallest (stable ties) ----------------
__global__ void k_topk(const float* __restrict__ D, int* __restrict__ outp) {
    int row  = blockIdx.x * 8 + (threadIdx.x >> 5);
    int lane = threadIdx.x & 31;
    const float* d = D + (size_t)row * NPT;
    float dist[KNN]; int ind[KNN];
#pragma unroll
    for (int p = 0; p < KNN; p++) { dist[p] = CUDART_INF_F; ind[p] = 0x7fffffff; }
    for (int j = lane; j < NPT; j += 32) {
        float v = d[j];
        if (v < dist[KNN - 1]) {
            float cd = v; int ci = j;
#pragma unroll
            for (int p = 0; p < KNN; p++) {
                if (cd < dist[p]) {
                    float td = dist[p]; int ti = ind[p];
                    dist[p] = cd; ind[p] = ci; cd = td; ci = ti;
                }
            }
        }
    }
    for (int r = 0; r < KNN; r++) {
        float cd = dist[0]; int ci = ind[0];
#pragma unroll
        for (int off = 16; off > 0; off >>= 1) {
            float od = __shfl_xor_sync(0xffffffffu, cd, off);
            int   oi = __shfl_xor_sync(0xffffffffu, ci, off);
            if (od < cd || (od == cd && oi < ci)) { cd = od; ci = oi; }
        }
        if (dist[0] == cd && ind[0] == ci) {
#pragma unroll
            for (int p = 0; p < KNN - 1; p++) { dist[p] = dist[p + 1]; ind[p] = ind[p + 1]; }
            dist[KNN - 1] = CUDART_INF_F; ind[KNN - 1] = 0x7fffffff;
        }
        if (lane == 0) outp[row * KNN + r] = ci;
    }
}

// ---------------- Wc = W[:, C:] - W[:, :C] ----------------
__global__ void k_wc(const float* __restrict__ W, int O, int C, float* __restrict__ Wc) {
    int i = blockIdx.x * 256 + threadIdx.x;
    if (i >= O * C) return;
    int o = i / C, c = i - o * C;
    Wc[i] = W[(size_t)o * 2 * C + C + c] - W[(size_t)o * 2 * C + c];
}

// ---------------- 3xtf32 mma NT GEMM (pre-split packed operands) ----------------------
// grid (NB/64, O/64), block 128; K multiple of 32. act==1: lrelu(s*(acc+extra)+b)
__global__ void k_mma(const uint32_t* __restrict__ Ah, const uint32_t* __restrict__ Al,
                      const uint32_t* __restrict__ Wh, const uint32_t* __restrict__ Wl,
                      int Kdim, int Odim,
                      const float* __restrict__ scale, const float* __restrict__ bias,
                      const float* __restrict__ extra,
                      float* __restrict__ outp, int rsOut, int act) {
    int m0 = blockIdx.x * 64, n0 = blockIdx.y * 64;
    __shared__ uint32_t sAh[64 * SPAD];
    __shared__ uint32_t sAl[64 * SPAD];
    __shared__ uint32_t sBh[64 * SPAD];
    __shared__ uint32_t sBl[64 * SPAD];
    int t = threadIdx.x;
    int warp = t >> 5, lane = t & 31;
    int g = lane >> 2, tg = lane & 3;
    int wm = (warp & 1) * 32, wn = (warp >> 1) * 32;
    float acc[2][4][4] = {};
    int lr = t >> 3, lc = (t & 7) * 4;
    for (int k0 = 0; k0 < Kdim; k0 += 32) {
#pragma unroll
        for (int rr = 0; rr < 64; rr += 16) {
            *(uint4*)&sAh[(lr + rr) * SPAD + lc] =
                *(const uint4*)(Ah + (size_t)(m0 + lr + rr) * Kdim + k0 + lc);
            *(uint4*)&sAl[(lr + rr) * SPAD + lc] =
                *(const uint4*)(Al + (size_t)(m0 + lr + rr) * Kdim + k0 + lc);
            *(uint4*)&sBh[(lr + rr) * SPAD + lc] =
                *(const uint4*)(Wh + (size_t)(n0 + lr + rr) * Kdim + k0 + lc);
            *(uint4*)&sBl[(lr + rr) * SPAD + lc] =
                *(const uint4*)(Wl + (size_t)(n0 + lr + rr) * Kdim + k0 + lc);
        }
        __syncthreads();
#pragma unroll
        for (int kk = 0; kk < 32; kk += 8) {
            uint32_t afh[2][4], afl[2][4], bfh[4][2], bfl[4][2];
#pragma unroll
            for (int mt = 0; mt < 2; mt++) {
                int r0 = (wm + mt * 16 + g) * SPAD + kk + tg;
                int r1 = (wm + mt * 16 + g + 8) * SPAD + kk + tg;
                afh[mt][0] = sAh[r0]; afh[mt][1] = sAh[r1];
                afh[mt][2] = sAh[r0 + 4]; afh[mt][3] = sAh[r1 + 4];
                afl[mt][0] = sAl[r0]; afl[mt][1] = sAl[r1];
                afl[mt][2] = sAl[r0 + 4]; afl[mt][3] = sAl[r1 + 4];
            }
#pragma unroll
            for (int nt = 0; nt < 4; nt++) {
                int r0 = (wn + nt * 8 + g) * SPAD + kk + tg;
                bfh[nt][0] = sBh[r0]; bfh[nt][1] = sBh[r0 + 4];
                bfl[nt][0] = sBl[r0]; bfl[nt][1] = sBl[r0 + 4];
            }
#pragma unroll
            for (int mt = 0; mt < 2; mt++)
#pragma unroll
                for (int nt = 0; nt < 4; nt++) {
                    mma8(acc[mt][nt], afh[mt], bfl[nt]);
                    mma8(acc[mt][nt], afl[mt], bfh[nt]);
                    mma8(acc[mt][nt], afh[mt], bfh[nt]);
                }
        }
        __syncthreads();
    }
#pragma unroll
    for (int mt = 0; mt < 2; mt++)
#pragma unroll
        for (int rh = 0; rh < 2; rh++) {
            int m = m0 + wm + mt * 16 + g + rh * 8;
            int bat = m >> 12;
#pragma unroll
            for (int nt = 0; nt < 4; nt++) {
                int o = n0 + wn + nt * 8 + tg * 2;
                float v0 = acc[mt][nt][rh * 2 + 0];
                float v1 = acc[mt][nt][rh * 2 + 1];
                if (act) {
                    if (extra) { v0 += extra[bat * Odim + o]; v1 += extra[bat * Odim + o + 1]; }
                    v0 = v0 * scale[o] + bias[o];
                    v1 = v1 * scale[o + 1] + bias[o + 1];
                    v0 = v0 > 0.f ? v0 : 0.2f * v0;
                    v1 = v1 > 0.f ? v1 : 0.2f * v1;
                }
                *(float2*)(outp + (size_t)m * rsOut + o) = make_float2(v0, v1);
            }
        }
}

// ---------------- 3xtf32 mma edge conv (layers 2-4) ----------------
// block: 16 points x 20 nbrs = 320 gathered rows x 64 out-cols; 10 warps (warp tile 32x64)
// out = lrelu(s*(max_k Wd.nbr_k + base)+b); grid (NB/16, O/64), dynamic smem
__global__ void __launch_bounds__(320, 1)
k_edge_mma(const uint32_t* __restrict__ Xh, const uint32_t* __restrict__ Xl, int C,
           const int* __restrict__ idx,
           const uint32_t* __restrict__ Wdh, const uint32_t* __restrict__ Wdl, int Odim,
           const float* __restrict__ base,
           const float* __restrict__ scale, const float* __restrict__ bias,
           float* __restrict__ outp, int rsOut) {
    extern __shared__ uint32_t esm[];
    uint32_t* sNh = esm;                                  // 320*SPAD
    uint32_t* sNl = esm + 320 * SPAD;                     // 320*SPAD
    uint32_t* sWh = esm + 2 * 320 * SPAD;                 // 64*SPAD
    uint32_t* sWl = esm + 2 * 320 * SPAD + 64 * SPAD;     // 64*SPAD
    float*    sRed = (float*)esm;                          // 320*65 (aliases sNh/sNl)
    __shared__ int sIdx[320];

    int p0 = blockIdx.x * 16;           // first point of block
    int o0 = blockIdx.y * 64;
    int t = threadIdx.x;
    int warp = t >> 5, lane = t & 31;
    int g = lane >> 2, tg = lane & 3;

    {   // neighbor indices (+ batch offset)
        int pt = p0 + t / KNN;
        int b  = pt >> 12;
        sIdx[t] = b * NPT + idx[(size_t)p0 * KNN + t];
    }
    __syncthreads();

    float acc[2][8][4] = {};
    for (int c0 = 0; c0 < C; c0 += 32) {
        // gather 320 neighbor rows (32 channels each), hi+lo
#pragma unroll 8
        for (int rr = 0; rr < 32; rr++) {
            int row = warp * 32 + rr;
            size_t src = (size_t)sIdx[row] * C + c0 + lane;
            sNh[row * SPAD + lane] = Xh[src];
            sNl[row * SPAD + lane] = Xl[src];
        }
        // W tile 64x32
        for (int i2 = t; i2 < 64 * 32; i2 += 320) {
            int r = i2 >> 5, c = i2 & 31;
            size_t src = (size_t)(o0 + r) * C + c0 + c;
            sWh[r * SPAD + c] = Wdh[src];
            sWl[r * SPAD + c] = Wdl[src];
        }
        __syncthreads();
#pragma unroll
        for (int kk = 0; kk < 32; kk += 8) {
            uint32_t afh[2][4], afl[2][4], bfh[8][2], bfl[8][2];
#pragma unroll
            for (int mt = 0; mt < 2; mt++) {
                int r0 = (warp * 32 + mt * 16 + g) * SPAD + kk + tg;
                int r1 = (warp * 32 + mt * 16 + g + 8) * SPAD + kk + tg;
                afh[mt][0] = sNh[r0]; afh[mt][1] = sNh[r1];
                afh[mt][2] = sNh[r0 + 4]; afh[mt][3] = sNh[r1 + 4];
                afl[mt][0] = sNl[r0]; afl[mt][1] = sNl[r1];
                afl[mt][2] = sNl[r0 + 4]; afl[mt][3] = sNl[r1 + 4];
            }
#pragma unroll
            for (int nt = 0; nt < 8; nt++) {
                int r0 = (nt * 8 + g) * SPAD + kk + tg;
                bfh[nt][0] = sWh[r0]; bfh[nt][1] = sWh[r0 + 4];
                bfl[nt][0] = sWl[r0]; bfl[nt][1] = sWl[r0 + 4];
            }
#pragma unroll
            for (int mt = 0; mt < 2; mt++)
#pragma unroll
                for (int nt = 0; nt < 8; nt++) {
                    mma8(acc[mt][nt], afh[mt], bfl[nt]);
                    mma8(acc[mt][nt], afl[mt], bfh[nt]);
                    mma8(acc[mt][nt], afh[mt], bfh[nt]);
                }
        }
        __syncthreads();
    }
    // dump acc -> sRed[row][o], stride 65
#pragma unroll
    for (int mt = 0; mt < 2; mt++)
#pragma unroll
        for (int rh = 0; rh < 2; rh++) {
            int row = warp * 32 + mt * 16 + g + rh * 8;
#pragma unroll
            for (int nt = 0; nt < 8; nt++) {
                int o = nt * 8 + tg * 2;
                sRed[row * 65 + o]     = acc[mt][nt][rh * 2 + 0];
                sRed[row * 65 + o + 1] = acc[mt][nt][rh * 2 + 1];
            }
        }
    __syncthreads();
    // max over 20 nbrs, + base, scale/bias, lrelu
    for (int oi = t; oi < 16 * 64; oi += 320) {
        int pl = oi >> 6, ol = oi & 63;
        const float* r = &sRed[(pl * KNN) * 65 + ol];
        float m = r[0];
#pragma unroll
        for (int kk = 1; kk < KNN; kk++) m = fmaxf(m, r[kk * 65]);
        int pt = p0 + pl;
        int o  = o0 + ol;
        float v = scale[o] * (m + base[(size_t)pt * Odim + o]) + bias[o];
        v = v > 0.f ? v : 0.2f * v;
        outp[(size_t)pt * rsOut + o] = v;
    }
}

// ---------------- edge conv layer 1 (C=3) ----------------
__global__ void k_edge1(const float* __restrict__ x, const int* __restrict__ idx,
                        const float* __restrict__ W1, const float* __restrict__ sc,
                        const float* __restrict__ bi, float* __restrict__ outp) {
    int pt = blockIdx.x;
    int b  = pt >> 12;
    int t  = threadIdx.x;
    __shared__ float snb[KNN][3];
    __shared__ float sx[3];
    if (t < KNN) {
        int nb = idx[pt * KNN + t];
        const float* src = x + (size_t)(b * NPT + nb) * 3;
        snb[t][0] = src[0]; snb[t][1] = src[1]; snb[t][2] = src[2];
    }
    if (t < 3) sx[t] = x[(size_t)pt * 3 + t];
    __syncthreads();
    float wd0 = W1[t * 6 + 0], wd1 = W1[t * 6 + 1], wd2 = W1[t * 6 + 2];
    float wc0 = W1[t * 6 + 3] - wd0, wc1 = W1[t * 6 + 4] - wd1, wc2 = W1[t * 6 + 5] - wd2;
    float m = -CUDART_INF_F;
#pragma unroll
    for (int k = 0; k < KNN; k++) {
        float v = wd0 * snb[k][0] + wd1 * snb[k][1] + wd2 * snb[k][2];
        m = fmaxf(m, v);
    }
    float v = sc[t] * (m + wc0 * sx[0] + wc1 * sx[1] + wc2 * sx[2]) + bi[t];
    v = v > 0.f ? v : 0.2f * v;
    outp[(size_t)pt * 512 + t] = v;
}

// ---------------- global max over N of g-activation ----------------
__global__ void k_rowmax(const float* __restrict__ actp, float* __restrict__ g) {
    int o = blockIdx.x * 256 + threadIdx.x;
    int b = blockIdx.y;
    const float* p = actp + (size_t)b * NPT * 1024 + o;
    float m0 = -CUDART_INF_F, m1 = m0, m2 = m0, m3 = m0;
    for (int n = 0; n < NPT; n += 4) {
        m0 = fmaxf(m0, p[(size_t)(n + 0) * 1024]);
        m1 = fmaxf(m1, p[(size_t)(n + 1) * 1024]);
        m2 = fmaxf(m2, p[(size_t)(n + 2) * 1024]);
        m3 = fmaxf(m3, p[(size_t)(n + 3) * 1024]);
    }
    g[b * 1024 + o] = fmaxf(fmaxf(m0, m1), fmaxf(m2, m3));
}

// ---------------- sterm[b][o] = Ws1[o, 512:1536] . g[b] ----------------
__global__ void k_sterm(const float* __restrict__ Ws1, const float* __restrict__ g,
                        float* __restrict__ st) {
    int i = blockIdx.x * 256 + threadIdx.x;
    if (i >= BATCH * 512) return;
    int b = i >> 9, o = i & 511;
    const float* w  = Ws1 + (size_t)o * 1536 + 512;
    const float* gb = g + b * 1024;
    float s = 0.f;
    for (int e = 0; e < 1024; e++) s = fmaf(w[e], gb[e], s);
    st[i] = s;
}

// ---------------- final classifier (O=13) ----------------
__global__ void k_out(const float* __restrict__ h2, const float* __restrict__ W3,
                      const float* __restrict__ b3, float* __restrict__ outp) {
    __shared__ float sW[13 * 256];
    __shared__ float sb[13];
    int t = threadIdx.x;
    for (int i = t; i < 13 * 256; i += 256) sW[i] = W3[i];
    if (t < 13) sb[t] = b3[t];
    __syncthreads();
    int m = blockIdx.x * 256 + t;
    float acc[13];
#pragma unroll
    for (int c = 0; c < 13; c++) acc[c] = 0.f;
    const float* h = h2 + (size_t)m * 256;
    for (int k = 0; k < 256; k++) {
        float xv = h[k];
#pragma unroll
        for (int c = 0; c < 13; c++) acc[c] = fmaf(xv, sW[c * 256 + k], acc[c]);
    }
#pragma unroll
    for (int c = 0; c < 13; c++) outp[(size_t)m * 13 + c] = acc[c] + sb[c];
}

// ---------------- host ----------------
#define EDGE_SMEM ((2 * 320 * SPAD + 2 * 64 * SPAD) * 4)

static void edge_layer(float* xcat, int inOff, int C,
                       const float* W, const float* s, const float* b,
                       int O, int outOff,
                       float* xxp, float* distp, int* idxp, float* wcp, float* basep,
                       uint32_t* Xh, uint32_t* Xl, uint32_t* Wh, uint32_t* Wl) {
    k_sqnorm<<<NB / 256, 256>>>(xcat + inOff, 512, C, xxp);
    k_split<<<1024, 256>>>(xcat + inOff, NB, C, 512, Xh, Xl);
    k_dist_mma<<<dim3(NPT / 64, NPT / 64, BATCH), 128>>>(Xh, Xl, C, xxp, distp);
    k_topk<<<NB / 8, 256>>>(distp, idxp);
    // base = Xin . Wc^T
    k_wc<<<(O * C + 255) / 256, 256>>>(W, O, C, wcp);
    k_split<<<256, 256>>>(wcp, O, C, C, Wh, Wl);
    k_mma<<<dim3(NB / 64, O / 64), 128>>>(Xh, Xl, Wh, Wl, C, O,
                                          nullptr, nullptr, nullptr, basep, O, 0);
    // edge: max_k Wd . nbr_k  (Wd = W[:, :C], row stride 2C)
    k_split<<<256, 256>>>(W, O, C, 2 * C, Wh, Wl);
    k_edge_mma<<<dim3(NB / 16, O / 64), 320, EDGE_SMEM>>>(
        Xh, Xl, C, idxp, Wh, Wl, O, basep, s, b, xcat + outOff, 512);
}

extern "C" void kernel_launch(void* const* d_in, const int* in_sizes, int n_in,
                              void* d_out, int out_size) {
    const float* x   = (const float*)d_in[0];
    const float* W1  = (const float*)d_in[1];
    const float* s1  = (const float*)d_in[2];
    const float* b1  = (const float*)d_in[3];
    const float* W2  = (const float*)d_in[4];
    const float* s2  = (const float*)d_in[5];
    const float* b2  = (const float*)d_in[6];
    const float* W3  = (const float*)d_in[7];
    const float* s3  = (const float*)d_in[8];
    const float* b3  = (const float*)d_in[9];
    const float* W4  = (const float*)d_in[10];
    const float* s4  = (const float*)d_in[11];
    const float* b4  = (const float*)d_in[12];
    const float* Wg  = (const float*)d_in[13];
    const float* sg  = (const float*)d_in[14];
    const float* bg  = (const float*)d_in[15];
    const float* Ws1 = (const float*)d_in[16];
    const float* ss1 = (const float*)d_in[17];
    const float* bs1 = (const float*)d_in[18];
    const float* Ws2 = (const float*)d_in[19];
    const float* ss2 = (const float*)d_in[20];
    const float* bs2 = (const float*)d_in[21];
    const float* Ws3 = (const float*)d_in[22];
    const float* bs3 = (const float*)d_in[23];
    float* outp = (float*)d_out;

    float *dist, *xx, *xcat, *base, *wc, *act, *gvec, *sterm, *h1, *h2;
    uint32_t *Xh, *Xl, *Wh, *Wl;
    int* idxp;
    cudaGetSymbolAddress((void**)&dist,  g_dist);
    cudaGetSymbolAddress((void**)&idxp,  g_idx);
    cudaGetSymbolAddress((void**)&xx,    g_xx);
    cudaGetSymbolAddress((void**)&xcat,  g_xcat);
    cudaGetSymbolAddress((void**)&base,  g_base);
    cudaGetSymbolAddress((void**)&wc,    g_Wc);
    cudaGetSymbolAddress((void**)&Xh,    g_Xh);
    cudaGetSymbolAddress((void**)&Xl,    g_Xl);
    cudaGetSymbolAddress((void**)&Wh,    g_Wh);
    cudaGetSymbolAddress((void**)&Wl,    g_Wl);
    cudaGetSymbolAddress((void**)&act,   g_act);
    cudaGetSymbolAddress((void**)&gvec,  g_gvec);
    cudaGetSymbolAddress((void**)&sterm, g_sterm);
    cudaGetSymbolAddress((void**)&h1,    g_h1);
    cudaGetSymbolAddress((void**)&h2,    g_h2);

    cudaFuncSetAttribute(k_edge_mma, cudaFuncAttributeMaxDynamicSharedMemorySize, EDGE_SMEM);

    // Layer 1 (kNN on raw xyz, C=3, O=64 -> xcat[:, 0:64])
    k_sqnorm<<<NB / 256, 256>>>(x, 3, 3, xx);
    k_dist3<<<dim3(NPT / 64, NPT / 64, BATCH), 128>>>(x, xx, dist);
    k_topk<<<NB / 8, 256>>>(dist, idxp);
    k_edge1<<<NB, 64>>>(x, idxp, W1, s1, b1, xcat);

    // Layers 2-4 (tensor-core path)
    edge_layer(xcat, 0,   64,  W2, s2, b2, 64,  64,  xx, dist, idxp, wc, base, Xh, Xl, Wh, Wl);
    edge_layer(xcat, 64,  64,  W3, s3, b3, 128, 128, xx, dist, idxp, wc, base, Xh, Xl, Wh, Wl);
    edge_layer(xcat, 128, 128, W4, s4, b4, 256, 256, xx, dist, idxp, wc, base, Xh, Xl, Wh, Wl);

    // Split full xcat once; reused for Wg and Ws1 GEMMs
    k_split<<<2048, 256>>>(xcat, NB, 512, 512, Xh, Xl);

    // Global feature: g = max_n lrelu(sg*(xcat.Wg^T)+bg)
    k_split<<<2048, 256>>>(Wg, 1024, 512, 512, Wh, Wl);
    k_mma<<<dim3(NB / 64, 1024 / 64), 128>>>(Xh, Xl, Wh, Wl, 512, 1024,
                                             sg, bg, nullptr, act, 1024, 1);
    k_rowmax<<<dim3(4, BATCH), 256>>>(act, gvec);

    // Ws1: split [xcat ; g] -> GEMM on xcat + per-batch sterm from g
    k_sterm<<<4, 256>>>(Ws1, gvec, sterm);
    k_split<<<1024, 256>>>(Ws1, 512, 512, 1536, Wh, Wl);
    k_mma<<<dim3(NB / 64, 512 / 64), 128>>>(Xh, Xl, Wh, Wl, 512, 512,
                                            ss1, bs1, sterm, h1, 512, 1);
    // Ws2
    k_split<<<2048, 256>>>(h1, NB, 512, 512, Xh, Xl);
    k_split<<<512, 256>>>(Ws2, 256, 512, 512, Wh, Wl);
    k_mma<<<dim3(NB / 64, 256 / 64), 128>>>(Xh, Xl, Wh, Wl, 512, 256,
                                            ss2, bs2, nullptr, h2, 256, 1);
    // Ws3 (13 classes) + bias
    k_out<<<NB / 256, 256>>>(h2, Ws3, bs3, outp);
}

// round 6
// speedup vs baseline: 1.2495x; 1.2495x over previous
#include <cuda_runtime.h>
#include <math_constants.h>
#include <cstdint>
#include <cstddef>

#define BATCH 2
#define NPT   4096
#define NB    (BATCH * NPT)
#define KNN   20
#define TCAP  512

// ---------------- scratch (device globals; no allocation) ----------------
__device__ float g_dist[(size_t)NB * NPT];     // 134 MB distance matrix (reused per layer)
__device__ int   g_idx[NB * KNN];
__device__ float g_xx[NB];
__device__ float g_xcat[(size_t)NB * 512];     // x1|x2|x3|x4 at channel offsets 0/64/128/256
__device__ float g_base[(size_t)NB * 256];
__device__ float g_Wc[256 * 128];
__device__ float g_act[(size_t)NB * 1024];
__device__ float g_gvec[BATCH * 1024];
__device__ float g_sterm[BATCH * 512];
__device__ float g_h1[(size_t)NB * 512];
__device__ float g_h2[(size_t)NB * 256];

// ---------------- squared norms ----------------
__global__ void k_sqnorm(const float* __restrict__ X, int rs, int C, float* __restrict__ xx) {
    int i = blockIdx.x * blockDim.x + threadIdx.x;
    if (i >= NB) return;
    const float* r = X + (size_t)i * rs;
    float s = 0.f;
    for (int c = 0; c < C; c++) s = fmaf(r[c], r[c], s);
    xx[i] = s;
}

// ---------------- pairwise distance matrix: D = xx_i + xx_j - 2 * X X^T ----------------
// grid (N/64, N/64, B), block 128; 64x64 tile, k-chunks of 16, 8x4 micro-tile per thread
__global__ void k_dist(const float* __restrict__ X, int rs, int C,
                       const float* __restrict__ xx, float* __restrict__ D) {
    int bi = blockIdx.x * 64;
    int bj = blockIdx.y * 64;
    int b  = blockIdx.z;
    const float* Xb  = X  + (size_t)b * NPT * rs;
    const float* xxb = xx + b * NPT;
    __shared__ float sA[16][68];
    __shared__ float sB[16][68];
    float acc[8][4];
#pragma unroll
    for (int i = 0; i < 8; i++)
#pragma unroll
        for (int j = 0; j < 4; j++) acc[i][j] = 0.f;
    int t  = threadIdx.x;
    int mi = t & 7, oj = t >> 3;
    int lr = t >> 1, lk = (t & 1) * 8;
    for (int k0 = 0; k0 < C; k0 += 16) {
        const float* ar = Xb + (size_t)(bi + lr) * rs + k0 + lk;
        const float* br = Xb + (size_t)(bj + lr) * rs + k0 + lk;
#pragma unroll
        for (int q = 0; q < 8; q++) {
            int kg = k0 + lk + q;
            float va = 0.f, vb = 0.f;
            if (kg < C) { va = ar[q]; vb = br[q]; }
            sA[lk + q][lr] = va;
            sB[lk + q][lr] = vb;
        }
        __syncthreads();
#pragma unroll
        for (int kk = 0; kk < 16; kk++) {
            float4 a0 = *(const float4*)&sA[kk][mi * 8];
            float4 a1 = *(const float4*)&sA[kk][mi * 8 + 4];
            float4 bq = *(const float4*)&sB[kk][oj * 4];
            float av[8] = {a0.x, a0.y, a0.z, a0.w, a1.x, a1.y, a1.z, a1.w};
            float bv[4] = {bq.x, bq.y, bq.z, bq.w};
#pragma unroll
            for (int i = 0; i < 8; i++)
#pragma unroll
                for (int j = 0; j < 4; j++) acc[i][j] = fmaf(av[i], bv[j], acc[i][j]);
        }
        __syncthreads();
    }
#pragma unroll
    for (int ri = 0; ri < 8; ri++) {
        int i = bi + mi * 8 + ri;
        float xi = xxb[i];
        float4 v;
        int j0 = bj + oj * 4;
        v.x = xi + xxb[j0 + 0] - 2.f * acc[ri][0];
        v.y = xi + xxb[j0 + 1] - 2.f * acc[ri][1];
        v.z = xi + xxb[j0 + 2] - 2.f * acc[ri][2];
        v.w = xi + xxb[j0 + 3] - 2.f * acc[ri][3];
        *(float4*)(D + ((size_t)b * NPT + i) * NPT + j0) = v;
    }
}

// ---------------- threshold-filtered exact top-20 smallest (stable ties) ----------------
// 1 warp/row. Sample first 256 -> t = 20th smallest of sample (>=20 values <= t exist).
// Compact v<=t into smem (exp ~320), exact stable select there. Fallback: full scan.
__global__ void k_topk(const float* __restrict__ D, int* __restrict__ outp) {
    __shared__ float sVal[8][TCAP];
    __shared__ int   sInd[8][TCAP];
    int w    = threadIdx.x >> 5;
    int row  = blockIdx.x * 8 + w;
    int lane = threadIdx.x & 31;
    const float* d = D + (size_t)row * NPT;

    // ---- pass 1: per-lane ascending sort of its 8 sample values ----
    float sd[8];
#pragma unroll
    for (int p = 0; p < 8; p++) sd[p] = CUDART_INF_F;
#pragma unroll
    for (int q = 0; q < 8; q++) {
        float cd = d[lane + q * 32];
#pragma unroll
        for (int p = 0; p < 8; p++) {
            if (cd < sd[p]) { float tm = sd[p]; sd[p] = cd; cd = tm; }
        }
    }
    // warp merge: 20 extraction rounds -> t (value of 20th smallest in sample)
    float t = CUDART_INF_F;
#pragma unroll 1
    for (int r = 0; r < KNN; r++) {
        float cd = sd[0]; int cl = lane;
#pragma unroll
        for (int off = 16; off > 0; off >>= 1) {
            float od = __shfl_xor_sync(0xffffffffu, cd, off);
            int   ol = __shfl_xor_sync(0xffffffffu, cl, off);
            if (od < cd || (od == cd && ol < cl)) { cd = od; cl = ol; }
        }
        if (lane == cl) {
#pragma unroll
            for (int p = 0; p < 7; p++) sd[p] = sd[p + 1];
            sd[7] = CUDART_INF_F;
        }
        t = cd;   // after reduce, all lanes hold the round's min; round 19 = threshold
    }

    // ---- pass 2: ballot-compact all v <= t into smem buffer ----
    int cnt = 0;
    for (int j = lane; j < NPT; j += 32) {
        float v = d[j];
        bool pr = (v <= t);
        unsigned mask = __ballot_sync(0xffffffffu, pr);
        if (pr) {
            int pos = cnt + __popc(mask & ((1u << lane) - 1u));
            if (pos < TCAP) { sVal[w][pos] = v; sInd[w][pos] = j; }
        }
        cnt += __popc(mask);
    }

    // ---- pass 3: exact stable top-20 ----
    float dist[KNN]; int ind[KNN];
#pragma unroll
    for (int p = 0; p < KNN; p++) { dist[p] = CUDART_INF_F; ind[p] = 0x7fffffff; }
    if (cnt <= TCAP) {
        for (int i = lane; i < cnt; i += 32) {
            float v = sVal[w][i];
            if (v < dist[KNN - 1]) {
                float cd = v; int ci = sInd[w][i];
#pragma unroll
                for (int p = 0; p < KNN; p++) {
                    if (cd < dist[p]) {
                        float td = dist[p]; int ti = ind[p];
                        dist[p] = cd; ind[p] = ci; cd = td; ci = ti;
                    }
                }
            }
        }
    } else {
        // fallback: full scan (rare)
        for (int j = lane; j < NPT; j += 32) {
            float v = d[j];
            if (v < dist[KNN - 1]) {
                float cd = v; int ci = j;
#pragma unroll
                for (int p = 0; p < KNN; p++) {
                    if (cd < dist[p]) {
                        float td = dist[p]; int ti = ind[p];
                        dist[p] = cd; ind[p] = ci; cd = td; ci = ti;
                    }
                }
            }
        }
    }
    // 20 extraction rounds with (value, index) tie-break
#pragma unroll 1
    for (int r = 0; r < KNN; r++) {
        float cd = dist[0]; int ci = ind[0];
#pragma unroll
        for (int off = 16; off > 0; off >>= 1) {
            float od = __shfl_xor_sync(0xffffffffu, cd, off);
            int   oi = __shfl_xor_sync(0xffffffffu, ci, off);
            if (od < cd || (od == cd && oi < ci)) { cd = od; ci = oi; }
        }
        if (dist[0] == cd && ind[0] == ci) {
#pragma unroll
            for (int p = 0; p < KNN - 1; p++) { dist[p] = dist[p + 1]; ind[p] = ind[p + 1]; }
            dist[KNN - 1] = CUDART_INF_F; ind[KNN - 1] = 0x7fffffff;
        }
        if (lane == 0) outp[row * KNN + r] = ci;
    }
}

// ---------------- Wc = W[:, C:] - W[:, :C] ----------------
__global__ void k_wc(const float* __restrict__ W, int O, int C, float* __restrict__ Wc) {
    int i = blockIdx.x * 256 + threadIdx.x;
    if (i >= O * C) return;
    int o = i / C, c = i - o * C;
    Wc[i] = W[(size_t)o * 2 * C + C + c] - W[(size_t)o * 2 * C + c];
}

// ---------------- generic fused NT GEMM: out[m][o] = post(sum_k A[m][k] W[o][k]) ----------
// grid (NB/64, O/64), block 128; K multiple of 16. act==1: lrelu(s*(acc+extra)+b)
__global__ void k_gemm(const float* __restrict__ A, int rsA,
                       const float* __restrict__ W, int rsW,
                       int Kdim, int Odim,
                       const float* __restrict__ scale, const float* __restrict__ bias,
                       const float* __restrict__ extra,
                       float* __restrict__ outp, int rsOut, int act) {
    int m0 = blockIdx.x * 64;
    int o0 = blockIdx.y * 64;
    __shared__ float sA[16][68];
    __shared__ float sW[16][68];
    float acc[8][4];
#pragma unroll
    for (int i = 0; i < 8; i++)
#pragma unroll
        for (int j = 0; j < 4; j++) acc[i][j] = 0.f;
    int t  = threadIdx.x;
    int mi = t & 7, oj = t >> 3;
    int lr = t >> 1, lk = (t & 1) * 8;
    for (int k0 = 0; k0 < Kdim; k0 += 16) {
        const float* ar = A + (size_t)(m0 + lr) * rsA + k0 + lk;
        const float* wr = W + (size_t)(o0 + lr) * rsW + k0 + lk;
#pragma unroll
        for (int q = 0; q < 8; q++) {
            sA[lk + q][lr] = ar[q];
            sW[lk + q][lr] = wr[q];
        }
        __syncthreads();
#pragma unroll
        for (int kk = 0; kk < 16; kk++) {
            float4 a0 = *(const float4*)&sA[kk][mi * 8];
            float4 a1 = *(const float4*)&sA[kk][mi * 8 + 4];
            float4 bq = *(const float4*)&sW[kk][oj * 4];
            float av[8] = {a0.x, a0.y, a0.z, a0.w, a1.x, a1.y, a1.z, a1.w};
            float bv[4] = {bq.x, bq.y, bq.z, bq.w};
#pragma unroll
            for (int i = 0; i < 8; i++)
#pragma unroll
                for (int j = 0; j < 4; j++) acc[i][j] = fmaf(av[i], bv[j], acc[i][j]);
        }
        __syncthreads();
    }
#pragma unroll
    for (int ri = 0; ri < 8; ri++) {
        int m = m0 + mi * 8 + ri;
        int bat = m >> 12;
        float vv[4];
#pragma unroll
        for (int c = 0; c < 4; c++) {
            int o = o0 + oj * 4 + c;
            float v = acc[ri][c];
            if (act) {
                if (extra) v += extra[bat * Odim + o];
                v = v * scale[o] + bias[o];
                v = v > 0.f ? v : 0.2f * v;
            }
            vv[c] = v;
        }
        *(float4*)(outp + (size_t)m * rsOut + o0 + oj * 4) =
            make_float4(vv[0], vv[1], vv[2], vv[3]);
    }
}

// ---------------- fused edge conv (layers 2-4) ----------------
// per block: 4 points x 64 output channels; out = lrelu(s*(max_k Wd.nbr_k + base)+b)
// grid (NB/4, O/64), block 256
__global__ void k_edge(const float* __restrict__ Xin, int rsIn,
                       const int* __restrict__ idx,
                       const float* __restrict__ W, int rsW, int C, int Odim,
                       const float* __restrict__ base,
                       const float* __restrict__ scale, const float* __restrict__ bias,
                       float* __restrict__ outp, int rsOut) {
    int p0 = blockIdx.x * 4;
    int o0 = blockIdx.y * 64;
    int b  = p0 >> 12;
    __shared__ float sW[32][68];
    __shared__ float sN[32][85];
    __shared__ int   sIdx[80];
    __shared__ float sRed[4][64][4];
    int t = threadIdx.x;
    if (t < 80) sIdx[t] = idx[p0 * KNN + t];
    __syncthreads();
    float acc[4][5];
#pragma unroll
    for (int i = 0; i < 4; i++)
#pragma unroll
        for (int j = 0; j < 5; j++) acc[i][j] = 0.f;
    int og = t & 15;
    int kpg = t >> 4;
    for (int c0 = 0; c0 < C; c0 += 32) {
        {
            int r = t >> 2;
            int cc0 = (t & 3) * 8;
            const float* wr = W + (size_t)(o0 + r) * rsW + c0 + cc0;
#pragma unroll
            for (int q = 0; q < 8; q++) sW[cc0 + q][r] = wr[q];
        }
        {
            int w = t >> 5, lane = t & 31;
#pragma unroll
            for (int rr = 0; rr < 10; rr++) {
                int kp = w * 10 + rr;
                int nb = sIdx[kp];
                sN[lane][kp] = Xin[((size_t)(b * NPT + nb)) * rsIn + c0 + lane];
            }
        }
        __syncthreads();
#pragma unroll 4
        for (int cc = 0; cc < 32; cc++) {
            float4 w4 = *(const float4*)&sW[cc][og * 4];
            float wv[4] = {w4.x, w4.y, w4.z, w4.w};
#pragma unroll
            for (int kk = 0; kk < 5; kk++) {
                float nv = sN[cc][kpg * 5 + kk];
#pragma unroll
                for (int oi = 0; oi < 4; oi++) acc[oi][kk] = fmaf(wv[oi], nv, acc[oi][kk]);
            }
        }
        __syncthreads();
    }
    int p = kpg >> 2, sub = kpg & 3;
#pragma unroll
    for (int oi = 0; oi < 4; oi++) {
        float m = acc[oi][0];
#pragma unroll
        for (int kk = 1; kk < 5; kk++) m = fmaxf(m, acc[oi][kk]);
        sRed[p][og * 4 + oi][sub] = m;
    }
    __syncthreads();
    int p2 = t >> 6, ol = t & 63;
    float m = fmaxf(fmaxf(sRed[p2][ol][0], sRed[p2][ol][1]),
                    fmaxf(sRed[p2][ol][2], sRed[p2][ol][3]));
    int o  = o0 + ol;
    int pt = p0 + p2;
    float v = scale[o] * (m + base[(size_t)pt * Odim + o]) + bias[o];
    v = v > 0.f ? v : 0.2f * v;
    outp[(size_t)pt * rsOut + o] = v;
}

// ---------------- edge conv layer 1 (C=3) ----------------
__global__ void k_edge1(const float* __restrict__ x, const int* __restrict__ idx,
                        const float* __restrict__ W1, const float* __restrict__ sc,
                        const float* __restrict__ bi, float* __restrict__ outp) {
    int pt = blockIdx.x;
    int b  = pt >> 12;
    int t  = threadIdx.x;
    __shared__ float snb[KNN][3];
    __shared__ float sx[3];
    if (t < KNN) {
        int nb = idx[pt * KNN + t];
        const float* src = x + (size_t)(b * NPT + nb) * 3;
        snb[t][0] = src[0]; snb[t][1] = src[1]; snb[t][2] = src[2];
    }
    if (t < 3) sx[t] = x[(size_t)pt * 3 + t];
    __syncthreads();
    float wd0 = W1[t * 6 + 0], wd1 = W1[t * 6 + 1], wd2 = W1[t * 6 + 2];
    float wc0 = W1[t * 6 + 3] - wd0, wc1 = W1[t * 6 + 4] - wd1, wc2 = W1[t * 6 + 5] - wd2;
    float m = -CUDART_INF_F;
#pragma unroll
    for (int k = 0; k < KNN; k++) {
        float v = wd0 * snb[k][0] + wd1 * snb[k][1] + wd2 * snb[k][2];
        m = fmaxf(m, v);
    }
    float v = sc[t] * (m + wc0 * sx[0] + wc1 * sx[1] + wc2 * sx[2]) + bi[t];
    v = v > 0.f ? v : 0.2f * v;
    outp[(size_t)pt * 512 + t] = v;
}

// ---------------- global max over N of g-activation ----------------
__global__ void k_rowmax(const float* __restrict__ actp, float* __restrict__ g) {
    int o = blockIdx.x * 256 + threadIdx.x;
    int b = blockIdx.y;
    const float* p = actp + (size_t)b * NPT * 1024 + o;
    float m0 = -CUDART_INF_F, m1 = m0, m2 = m0, m3 = m0;
    for (int n = 0; n < NPT; n += 4) {
        m0 = fmaxf(m0, p[(size_t)(n + 0) * 1024]);
        m1 = fmaxf(m1, p[(size_t)(n + 1) * 1024]);
        m2 = fmaxf(m2, p[(size_t)(n + 2) * 1024]);
        m3 = fmaxf(m3, p[(size_t)(n + 3) * 1024]);
    }
    g[b * 1024 + o] = fmaxf(fmaxf(m0, m1), fmaxf(m2, m3));
}

// ---------------- sterm[b][o] = Ws1[o, 512:1536] . g[b] ----------------
__global__ void k_sterm(const float* __restrict__ Ws1, const float* __restrict__ g,
                        float* __restrict__ st) {
    int i = blockIdx.x * 256 + threadIdx.x;
    if (i >= BATCH * 512) return;
    int b = i >> 9, o = i & 511;
    const float* w  = Ws1 + (size_t)o * 1536 + 512;
    const float* gb = g + b * 1024;
    float s = 0.f;
    for (int e = 0; e < 1024; e++) s = fmaf(w[e], gb[e], s);
    st[i] = s;
}

// ---------------- final classifier (O=13) ----------------
__global__ void k_out(const float* __restrict__ h2, const float* __restrict__ W3,
                      const float* __restrict__ b3, float* __restrict__ outp) {
    __shared__ float sW[13 * 256];
    __shared__ float sb[13];
    int t = threadIdx.x;
    for (int i = t; i < 13 * 256; i += 256) sW[i] = W3[i];
    if (t < 13) sb[t] = b3[t];
    __syncthreads();
    int m = blockIdx.x * 256 + t;
    float acc[13];
#pragma unroll
    for (int c = 0; c < 13; c++) acc[c] = 0.f;
    const float* h = h2 + (size_t)m * 256;
    for (int k = 0; k < 256; k++) {
        float xv = h[k];
#pragma unroll
        for (int c = 0; c < 13; c++) acc[c] = fmaf(xv, sW[c * 256 + k], acc[c]);
    }
#pragma unroll
    for (int c = 0; c < 13; c++) outp[(size_t)m * 13 + c] = acc[c] + sb[c];
}

// ---------------- host ----------------
static void edge_layer(float* xcat, int inOff, int C,
                       const float* W, const float* s, const float* b,
                       int O, int outOff,
                       float* xxp, float* distp, int* idxp, float* wcp, float* basep) {
    k_sqnorm<<<NB / 256, 256>>>(xcat + inOff, 512, C, xxp);
    k_dist<<<dim3(NPT / 64, NPT / 64, BATCH), 128>>>(xcat + inOff, 512, C, xxp, distp);
    k_topk<<<NB / 8, 256>>>(distp, idxp);
    k_wc<<<(O * C + 255) / 256, 256>>>(W, O, C, wcp);
    k_gemm<<<dim3(NB / 64, O / 64), 128>>>(xcat + inOff, 512, wcp, C, C, O,
                                           nullptr, nullptr, nullptr, basep, O, 0);
    k_edge<<<dim3(NB / 4, O / 64), 256>>>(xcat + inOff, 512, idxp, W, 2 * C, C, O,
                                          basep, s, b, xcat + outOff, 512);
}

extern "C" void kernel_launch(void* const* d_in, const int* in_sizes, int n_in,
                              void* d_out, int out_size) {
    const float* x   = (const float*)d_in[0];
    const float* W1  = (const float*)d_in[1];
    const float* s1  = (const float*)d_in[2];
    const float* b1  = (const float*)d_in[3];
    const float* W2  = (const float*)d_in[4];
    const float* s2  = (const float*)d_in[5];
    const float* b2  = (const float*)d_in[6];
    const float* W3  = (const float*)d_in[7];
    const float* s3  = (const float*)d_in[8];
    const float* b3  = (const float*)d_in[9];
    const float* W4  = (const float*)d_in[10];
    const float* s4  = (const float*)d_in[11];
    const float* b4  = (const float*)d_in[12];
    const float* Wg  = (const float*)d_in[13];
    const float* sg  = (const float*)d_in[14];
    const float* bg  = (const float*)d_in[15];
    const float* Ws1 = (const float*)d_in[16];
    const float* ss1 = (const float*)d_in[17];
    const float* bs1 = (const float*)d_in[18];
    const float* Ws2 = (const float*)d_in[19];
    const float* ss2 = (const float*)d_in[20];
    const float* bs2 = (const float*)d_in[21];
    const float* Ws3 = (const float*)d_in[22];
    const float* bs3 = (const float*)d_in[23];
    float* outp = (float*)d_out;

    float *dist, *xx, *xcat, *base, *wc, *act, *gvec, *sterm, *h1, *h2;
    int* idxp;
    cudaGetSymbolAddress((void**)&dist,  g_dist);
    cudaGetSymbolAddress((void**)&idxp,  g_idx);
    cudaGetSymbolAddress((void**)&xx,    g_xx);
    cudaGetSymbolAddress((void**)&xcat,  g_xcat);
    cudaGetSymbolAddress((void**)&base,  g_base);
    cudaGetSymbolAddress((void**)&wc,    g_Wc);
    cudaGetSymbolAddress((void**)&act,   g_act);
    cudaGetSymbolAddress((void**)&gvec,  g_gvec);
    cudaGetSymbolAddress((void**)&sterm, g_sterm);
    cudaGetSymbolAddress((void**)&h1,    g_h1);
    cudaGetSymbolAddress((void**)&h2,    g_h2);

    // Layer 1 (kNN on raw xyz, C=3, O=64 -> xcat[:, 0:64])
    k_sqnorm<<<NB / 256, 256>>>(x, 3, 3, xx);
    k_dist<<<dim3(NPT / 64, NPT / 64, BATCH), 128>>>(x, 3, 3, xx, dist);
    k_topk<<<NB / 8, 256>>>(dist, idxp);
    k_edge1<<<NB, 64>>>(x, idxp, W1, s1, b1, xcat);

    // Layers 2-4
    edge_layer(xcat, 0,   64,  W2, s2, b2, 64,  64,  xx, dist, idxp, wc, base);
    edge_layer(xcat, 64,  64,  W3, s3, b3, 128, 128, xx, dist, idxp, wc, base);
    edge_layer(xcat, 128, 128, W4, s4, b4, 256, 256, xx, dist, idxp, wc, base);

    // Global feature: g = max_n lrelu(sg*(xcat.Wg^T)+bg)
    k_gemm<<<dim3(NB / 64, 1024 / 64), 128>>>(xcat, 512, Wg, 512, 512, 1024,
                                              sg, bg, nullptr, act, 1024, 1);
    k_rowmax<<<dim3(4, BATCH), 256>>>(act, gvec);

    // Ws1: split [xcat ; g] -> GEMM on xcat + per-batch sterm from g
    k_sterm<<<4, 256>>>(Ws1, gvec, sterm);
    k_gemm<<<dim3(NB / 64, 512 / 64), 128>>>(xcat, 512, Ws1, 1536, 512, 512,
                                             ss1, bs1, sterm, h1, 512, 1);
    // Ws2
    k_gemm<<<dim3(NB / 64, 256 / 64), 128>>>(h1, 512, Ws2, 512, 512, 256,
                                             ss2, bs2, nullptr, h2, 256, 1);
    // Ws3 (13 classes) + bias
    k_out<<<NB / 256, 256>>>(h2, Ws3, bs3, outp);
}

// round 7
// speedup vs baseline: 1.6498x; 1.3204x over previous
#include <cuda_runtime.h>
#include <math_constants.h>
#include <cstdint>
#include <cstddef>

#define BATCH 2
#define NPT   4096
#define NB    (BATCH * NPT)
#define KNN   20
#define TCAP  512

// ---------------- scratch (device globals; no allocation) ----------------
__device__ float g_dist[(size_t)NB * NPT];     // 134 MB distance matrix (reused per layer)
__device__ int   g_idx[NB * KNN];
__device__ float g_xx[NB];
__device__ float g_xcat[(size_t)NB * 512];     // x1|x2|x3|x4 at channel offsets 0/64/128/256
__device__ float g_base[(size_t)NB * 256];
__device__ float g_Wc[256 * 128];
__device__ float g_act[(size_t)NB * 1024];
__device__ float g_gvec[BATCH * 1024];
__device__ float g_sterm[BATCH * 512];
__device__ float g_h1[(size_t)NB * 512];
__device__ float g_h2[(size_t)NB * 256];

// ---------------- squared norms ----------------
__global__ void k_sqnorm(const float* __restrict__ X, int rs, int C, float* __restrict__ xx) {
    int i = blockIdx.x * blockDim.x + threadIdx.x;
    if (i >= NB) return;
    const float* r = X + (size_t)i * rs;
    float s = 0.f;
    for (int c = 0; c < C; c++) s = fmaf(r[c], r[c], s);
    xx[i] = s;
}

// ---------------- pairwise distance, 128x128 tile, split-tile 8x8/thread ----------------
// grid (NPT/128, NPT/128, B), block 256
__global__ void __launch_bounds__(256)
k_dist(const float* __restrict__ X, int rs, int C,
       const float* __restrict__ xx, float* __restrict__ D) {
    int m0 = blockIdx.x * 128;
    int n0 = blockIdx.y * 128;
    int b  = blockIdx.z;
    const float* Xb  = X  + (size_t)b * NPT * rs;
    const float* xxb = xx + b * NPT;
    __shared__ float sA[16][132];
    __shared__ float sB[16][132];
    float acc[8][8];
#pragma unroll
    for (int i = 0; i < 8; i++)
#pragma unroll
        for (int j = 0; j < 8; j++) acc[i][j] = 0.f;
    int t = threadIdx.x;
    int mi = t & 15, nj = t >> 4;
    for (int k0 = 0; k0 < C; k0 += 16) {
#pragma unroll 1
        for (int s = t; s < 256; s += 256) {
            int row = s >> 1, lk = (s & 1) * 8;
            const float* ar = Xb + (size_t)(m0 + row) * rs + k0 + lk;
            const float* br = Xb + (size_t)(n0 + row) * rs + k0 + lk;
#pragma unroll
            for (int q = 0; q < 8; q++) {
                bool ok = (k0 + lk + q) < C;
                sA[lk + q][row] = ok ? ar[q] : 0.f;
                sB[lk + q][row] = ok ? br[q] : 0.f;
            }
        }
        __syncthreads();
#pragma unroll
        for (int kk = 0; kk < 16; kk++) {
            float4 a0 = *(const float4*)&sA[kk][mi * 4];
            float4 a1 = *(const float4*)&sA[kk][64 + mi * 4];
            float4 b0 = *(const float4*)&sB[kk][nj * 4];
            float4 b1 = *(const float4*)&sB[kk][64 + nj * 4];
            float av[8] = {a0.x, a0.y, a0.z, a0.w, a1.x, a1.y, a1.z, a1.w};
            float bv[8] = {b0.x, b0.y, b0.z, b0.w, b1.x, b1.y, b1.z, b1.w};
#pragma unroll
            for (int i = 0; i < 8; i++)
#pragma unroll
                for (int j = 0; j < 8; j++) acc[i][j] = fmaf(av[i], bv[j], acc[i][j]);
        }
        __syncthreads();
    }
#pragma unroll
    for (int ih = 0; ih < 2; ih++)
#pragma unroll
        for (int i = 0; i < 4; i++) {
            int ig = m0 + ih * 64 + mi * 4 + i;
            float xi = xxb[ig];
            float* dst = D + ((size_t)b * NPT + ig) * NPT;
#pragma unroll
            for (int jh = 0; jh < 2; jh++) {
                int j0 = n0 + jh * 64 + nj * 4;
                float4 xj = *(const float4*)&xxb[j0];
                float4 v;
                v.x = xi + xj.x - 2.f * acc[ih * 4 + i][jh * 4 + 0];
                v.y = xi + xj.y - 2.f * acc[ih * 4 + i][jh * 4 + 1];
                v.z = xi + xj.z - 2.f * acc[ih * 4 + i][jh * 4 + 2];
                v.w = xi + xj.w - 2.f * acc[ih * 4 + i][jh * 4 + 3];
                *(float4*)(dst + j0) = v;
            }
        }
}

// ---------------- threshold-filtered exact top-20 smallest (stable ties) ----------------
__global__ void k_topk(const float* __restrict__ D, int* __restrict__ outp) {
    __shared__ float sVal[8][TCAP];
    __shared__ int   sInd[8][TCAP];
    int w    = threadIdx.x >> 5;
    int row  = blockIdx.x * 8 + w;
    int lane = threadIdx.x & 31;
    const float* d = D + (size_t)row * NPT;

    float sd[8];
#pragma unroll
    for (int p = 0; p < 8; p++) sd[p] = CUDART_INF_F;
#pragma unroll
    for (int q = 0; q < 8; q++) {
        float cd = d[lane + q * 32];
#pragma unroll
        for (int p = 0; p < 8; p++) {
            if (cd < sd[p]) { float tm = sd[p]; sd[p] = cd; cd = tm; }
        }
    }
    float t = CUDART_INF_F;
#pragma unroll 1
    for (int r = 0; r < KNN; r++) {
        float cd = sd[0]; int cl = lane;
#pragma unroll
        for (int off = 16; off > 0; off >>= 1) {
            float od = __shfl_xor_sync(0xffffffffu, cd, off);
            int   ol = __shfl_xor_sync(0xffffffffu, cl, off);
            if (od < cd || (od == cd && ol < cl)) { cd = od; cl = ol; }
        }
        if (lane == cl) {
#pragma unroll
            for (int p = 0; p < 7; p++) sd[p] = sd[p + 1];
            sd[7] = CUDART_INF_F;
        }
        t = cd;
    }

    int cnt = 0;
    for (int j = lane; j < NPT; j += 32) {
        float v = d[j];
        bool pr = (v <= t);
        unsigned mask = __ballot_sync(0xffffffffu, pr);
        if (pr) {
            int pos = cnt + __popc(mask & ((1u << lane) - 1u));
            if (pos < TCAP) { sVal[w][pos] = v; sInd[w][pos] = j; }
        }
        cnt += __popc(mask);
    }

    float dist[KNN]; int ind[KNN];
#pragma unroll
    for (int p = 0; p < KNN; p++) { dist[p] = CUDART_INF_F; ind[p] = 0x7fffffff; }
    if (cnt <= TCAP) {
        for (int i = lane; i < cnt; i += 32) {
            float v = sVal[w][i];
            if (v < dist[KNN - 1]) {
                float cd = v; int ci = sInd[w][i];
#pragma unroll
                for (int p = 0; p < KNN; p++) {
                    if (cd < dist[p]) {
                        float td = dist[p]; int ti = ind[p];
                        dist[p] = cd; ind[p] = ci; cd = td; ci = ti;
                    }
                }
            }
        }
    } else {
        for (int j = lane; j < NPT; j += 32) {
            float v = d[j];
            if (v < dist[KNN - 1]) {
                float cd = v; int ci = j;
#pragma unroll
                for (int p = 0; p < KNN; p++) {
                    if (cd < dist[p]) {
                        float td = dist[p]; int ti = ind[p];
                        dist[p] = cd; ind[p] = ci; cd = td; ci = ti;
                    }
                }
            }
        }
    }
#pragma unroll 1
    for (int r = 0; r < KNN; r++) {
        float cd = dist[0]; int ci = ind[0];
#pragma unroll
        for (int off = 16; off > 0; off >>= 1) {
            float od = __shfl_xor_sync(0xffffffffu, cd, off);
            int   oi = __shfl_xor_sync(0xffffffffu, ci, off);
            if (od < cd || (od == cd && oi < ci)) { cd = od; ci = oi; }
        }
        if (dist[0] == cd && ind[0] == ci) {
#pragma unroll
            for (int p = 0; p < KNN - 1; p++) { dist[p] = dist[p + 1]; ind[p] = ind[p + 1]; }
            dist[KNN - 1] = CUDART_INF_F; ind[KNN - 1] = 0x7fffffff;
        }
        if (lane == 0) outp[row * KNN + r] = ci;
    }
}

// ---------------- Wc = W[:, C:] - W[:, :C] ----------------
__global__ void k_wc(const float* __restrict__ W, int O, int C, float* __restrict__ Wc) {
    int i = blockIdx.x * 256 + threadIdx.x;
    if (i >= O * C) return;
    int o = i / C, c = i - o * C;
    Wc[i] = W[(size_t)o * 2 * C + C + c] - W[(size_t)o * 2 * C + c];
}

// ---------------- tiled NT GEMM, 128xBN tile, 8x8/thread split-tile --------------------
// grid (NB/128, O/BN), block 16*(BN/8); K multiple of 16. act: lrelu(s*(acc+extra)+b)
template <int BN>
__global__ void __launch_bounds__(16 * (BN / 8))
k_gemm(const float* __restrict__ A, int rsA,
       const float* __restrict__ W, int rsW,
       int Kdim, int Odim,
       const float* __restrict__ scale, const float* __restrict__ bias,
       const float* __restrict__ extra,
       float* __restrict__ outp, int rsOut, int act) {
    constexpr int T = 16 * (BN / 8);
    int m0 = blockIdx.x * 128;
    int o0 = blockIdx.y * BN;
    __shared__ float sA[16][132];
    __shared__ float sB[16][BN + 4];
    float acc[8][8];
#pragma unroll
    for (int i = 0; i < 8; i++)
#pragma unroll
        for (int j = 0; j < 8; j++) acc[i][j] = 0.f;
    int t = threadIdx.x;
    int mi = t & 15, nj = t >> 4;
    for (int k0 = 0; k0 < Kdim; k0 += 16) {
#pragma unroll 1
        for (int s = t; s < 256; s += T) {
            int row = s >> 1, lk = (s & 1) * 8;
            const float* ar = A + (size_t)(m0 + row) * rsA + k0 + lk;
#pragma unroll
            for (int q = 0; q < 8; q++) sA[lk + q][row] = ar[q];
        }
#pragma unroll 1
        for (int s = t; s < BN * 2; s += T) {
            int row = s >> 1, lk = (s & 1) * 8;
            const float* wr = W + (size_t)(o0 + row) * rsW + k0 + lk;
#pragma unroll
            for (int q = 0; q < 8; q++) sB[lk + q][row] = wr[q];
        }
        __syncthreads();
#pragma unroll
        for (int kk = 0; kk < 16; kk++) {
            float4 a0 = *(const float4*)&sA[kk][mi * 4];
            float4 a1 = *(const float4*)&sA[kk][64 + mi * 4];
            float4 b0 = *(const float4*)&sB[kk][nj * 4];
            float4 b1 = *(const float4*)&sB[kk][BN / 2 + nj * 4];
            float av[8] = {a0.x, a0.y, a0.z, a0.w, a1.x, a1.y, a1.z, a1.w};
            float bv[8] = {b0.x, b0.y, b0.z, b0.w, b1.x, b1.y, b1.z, b1.w};
#pragma unroll
            for (int i = 0; i < 8; i++)
#pragma unroll
                for (int j = 0; j < 8; j++) acc[i][j] = fmaf(av[i], bv[j], acc[i][j]);
        }
        __syncthreads();
    }
#pragma unroll
    for (int ih = 0; ih < 2; ih++)
#pragma unroll
        for (int i = 0; i < 4; i++) {
            int m = m0 + ih * 64 + mi * 4 + i;
            int bat = m >> 12;
#pragma unroll
            for (int jh = 0; jh < 2; jh++) {
                int ob = o0 + jh * (BN / 2) + nj * 4;
                float4 v;
                float* vv = &v.x;
#pragma unroll
                for (int c = 0; c < 4; c++) {
                    int o = ob + c;
                    float x = acc[ih * 4 + i][jh * 4 + c];
                    if (act) {
                        if (extra) x += extra[bat * Odim + o];
                        x = x * scale[o] + bias[o];
                        x = x > 0.f ? x : 0.2f * x;
                    }
                    vv[c] = x;
                }
                *(float4*)(outp + (size_t)m * rsOut + ob) = v;
            }
        }
}

// ---------------- fused edge conv (layers 2-4) ----------------
// per block: 4 points x 64 output channels; out = lrelu(s*(max_k Wd.nbr_k + base)+b)
__global__ void k_edge(const float* __restrict__ Xin, int rsIn,
                       const int* __restrict__ idx,
                       const float* __restrict__ W, int rsW, int C, int Odim,
                       const float* __restrict__ base,
                       const float* __restrict__ scale, const float* __restrict__ bias,
                       float* __restrict__ outp, int rsOut) {
    int p0 = blockIdx.x * 4;
    int o0 = blockIdx.y * 64;
    int b  = p0 >> 12;
    __shared__ float sW[32][68];
    __shared__ float sN[32][85];
    __shared__ int   sIdx[80];
    __shared__ float sRed[4][64][4];
    int t = threadIdx.x;
    if (t < 80) sIdx[t] = idx[p0 * KNN + t];
    __syncthreads();
    float acc[4][5];
#pragma unroll
    for (int i = 0; i < 4; i++)
#pragma unroll
        for (int j = 0; j < 5; j++) acc[i][j] = 0.f;
    int og = t & 15;
    int kpg = t >> 4;
    for (int c0 = 0; c0 < C; c0 += 32) {
        {
            int r = t >> 2;
            int cc0 = (t & 3) * 8;
            const float* wr = W + (size_t)(o0 + r) * rsW + c0 + cc0;
#pragma unroll
            for (int q = 0; q < 8; q++) sW[cc0 + q][r] = wr[q];
        }
        {
            int w = t >> 5, lane = t & 31;
#pragma unroll
            for (int rr = 0; rr < 10; rr++) {
                int kp = w * 10 + rr;
                int nb = sIdx[kp];
                sN[lane][kp] = Xin[((size_t)(b * NPT + nb)) * rsIn + c0 + lane];
            }
        }
        __syncthreads();
#pragma unroll 4
        for (int cc = 0; cc < 32; cc++) {
            float4 w4 = *(const float4*)&sW[cc][og * 4];
            float wv[4] = {w4.x, w4.y, w4.z, w4.w};
#pragma unroll
            for (int kk = 0; kk < 5; kk++) {
                float nv = sN[cc][kpg * 5 + kk];
#pragma unroll
                for (int oi = 0; oi < 4; oi++) acc[oi][kk] = fmaf(wv[oi], nv, acc[oi][kk]);
            }
        }
        __syncthreads();
    }
    int p = kpg >> 2, sub = kpg & 3;
#pragma unroll
    for (int oi = 0; oi < 4; oi++) {
        float m = acc[oi][0];
#pragma unroll
        for (int kk = 1; kk < 5; kk++) m = fmaxf(m, acc[oi][kk]);
        sRed[p][og * 4 + oi][sub] = m;
    }
    __syncthreads();
    int p2 = t >> 6, ol = t & 63;
    float m = fmaxf(fmaxf(sRed[p2][ol][0], sRed[p2][ol][1]),
                    fmaxf(sRed[p2][ol][2], sRed[p2][ol][3]));
    int o  = o0 + ol;
    int pt = p0 + p2;
    float v = scale[o] * (m + base[(size_t)pt * Odim + o]) + bias[o];
    v = v > 0.f ? v : 0.2f * v;
    outp[(size_t)pt * rsOut + o] = v;
}

// ---------------- edge conv layer 1 (C=3) ----------------
__global__ void k_edge1(const float* __restrict__ x, const int* __restrict__ idx,
                        const float* __restrict__ W1, const float* __restrict__ sc,
                        const float* __restrict__ bi, float* __restrict__ outp) {
    int pt = blockIdx.x;
    int b  = pt >> 12;
    int t  = threadIdx.x;
    __shared__ float snb[KNN][3];
    __shared__ float sx[3];
    if (t < KNN) {
        int nb = idx[pt * KNN + t];
        const float* src = x + (size_t)(b * NPT + nb) * 3;
        snb[t][0] = src[0]; snb[t][1] = src[1]; snb[t][2] = src[2];
    }
    if (t < 3) sx[t] = x[(size_t)pt * 3 + t];
    __syncthreads();
    float wd0 = W1[t * 6 + 0], wd1 = W1[t * 6 + 1], wd2 = W1[t * 6 + 2];
    float wc0 = W1[t * 6 + 3] - wd0, wc1 = W1[t * 6 + 4] - wd1, wc2 = W1[t * 6 + 5] - wd2;
    float m = -CUDART_INF_F;
#pragma unroll
    for (int k = 0; k < KNN; k++) {
        float v = wd0 * snb[k][0] + wd1 * snb[k][1] + wd2 * snb[k][2];
        m = fmaxf(m, v);
    }
    float v = sc[t] * (m + wc0 * sx[0] + wc1 * sx[1] + wc2 * sx[2]) + bi[t];
    v = v > 0.f ? v : 0.2f * v;
    outp[(size_t)pt * 512 + t] = v;
}

// ---------------- global max over N of g-activation ----------------
__global__ void k_rowmax(const float* __restrict__ actp, float* __restrict__ g) {
    int o = blockIdx.x * 256 + threadIdx.x;
    int b = blockIdx.y;
    const float* p = actp + (size_t)b * NPT * 1024 + o;
    float m0 = -CUDART_INF_F, m1 = m0, m2 = m0, m3 = m0;
    for (int n = 0; n < NPT; n += 4) {
        m0 = fmaxf(m0, p[(size_t)(n + 0) * 1024]);
        m1 = fmaxf(m1, p[(size_t)(n + 1) * 1024]);
        m2 = fmaxf(m2, p[(size_t)(n + 2) * 1024]);
        m3 = fmaxf(m3, p[(size_t)(n + 3) * 1024]);
    }
    g[b * 1024 + o] = fmaxf(fmaxf(m0, m1), fmaxf(m2, m3));
}

// ---------------- sterm[b][o] = Ws1[o, 512:1536] . g[b] ----------------
__global__ void k_sterm(const float* __restrict__ Ws1, const float* __restrict__ g,
                        float* __restrict__ st) {
    int i = blockIdx.x * 256 + threadIdx.x;
    if (i >= BATCH * 512) return;
    int b = i >> 9, o = i & 511;
    const float* w  = Ws1 + (size_t)o * 1536 + 512;
    const float* gb = g + b * 1024;
    float s = 0.f;
    for (int e = 0; e < 1024; e++) s = fmaf(w[e], gb[e], s);
    st[i] = s;
}

// ---------------- final classifier (O=13) ----------------
__global__ void k_out(const float* __restrict__ h2, const float* __restrict__ W3,
                      const float* __restrict__ b3, float* __restrict__ outp) {
    __shared__ float sW[13 * 256];
    __shared__ float sb[13];
    int t = threadIdx.x;
    for (int i = t; i < 13 * 256; i += 256) sW[i] = W3[i];
    if (t < 13) sb[t] = b3[t];
    __syncthreads();
    int m = blockIdx.x * 256 + t;
    float acc[13];
#pragma unroll
    for (int c = 0; c < 13; c++) acc[c] = 0.f;
    const float* h = h2 + (size_t)m * 256;
    for (int k = 0; k < 256; k++) {
        float xv = h[k];
#pragma unroll
        for (int c = 0; c < 13; c++) acc[c] = fmaf(xv, sW[c * 256 + k], acc[c]);
    }
#pragma unroll
    for (int c = 0; c < 13; c++) outp[(size_t)m * 13 + c] = acc[c] + sb[c];
}

// ---------------- host ----------------
static void edge_layer(float* xcat, int inOff, int C,
                       const float* W, const float* s, const float* b,
                       int O, int outOff,
                       float* xxp, float* distp, int* idxp, float* wcp, float* basep) {
    k_sqnorm<<<NB / 256, 256>>>(xcat + inOff, 512, C, xxp);
    k_dist<<<dim3(NPT / 128, NPT / 128, BATCH), 256>>>(xcat + inOff, 512, C, xxp, distp);
    k_topk<<<NB / 8, 256>>>(distp, idxp);
    k_wc<<<(O * C + 255) / 256, 256>>>(W, O, C, wcp);
    if (O % 128 == 0)
        k_gemm<128><<<dim3(NB / 128, O / 128), 256>>>(xcat + inOff, 512, wcp, C, C, O,
                                                      nullptr, nullptr, nullptr, basep, O, 0);
    else
        k_gemm<64><<<dim3(NB / 128, O / 64), 128>>>(xcat + inOff, 512, wcp, C, C, O,
                                                    nullptr, nullptr, nullptr, basep, O, 0);
    k_edge<<<dim3(NB / 4, O / 64), 256>>>(xcat + inOff, 512, idxp, W, 2 * C, C, O,
                                          basep, s, b, xcat + outOff, 512);
}

extern "C" void kernel_launch(void* const* d_in, const int* in_sizes, int n_in,
                              void* d_out, int out_size) {
    const float* x   = (const float*)d_in[0];
    const float* W1  = (const float*)d_in[1];
    const float* s1  = (const float*)d_in[2];
    const float* b1  = (const float*)d_in[3];
    const float* W2  = (const float*)d_in[4];
    const float* s2  = (const float*)d_in[5];
    const float* b2  = (const float*)d_in[6];
    const float* W3  = (const float*)d_in[7];
    const float* s3  = (const float*)d_in[8];
    const float* b3  = (const float*)d_in[9];
    const float* W4  = (const float*)d_in[10];
    const float* s4  = (const float*)d_in[11];
    const float* b4  = (const float*)d_in[12];
    const float* Wg  = (const float*)d_in[13];
    const float* sg  = (const float*)d_in[14];
    const float* bg  = (const float*)d_in[15];
    const float* Ws1 = (const float*)d_in[16];
    const float* ss1 = (const float*)d_in[17];
    const float* bs1 = (const float*)d_in[18];
    const float* Ws2 = (const float*)d_in[19];
    const float* ss2 = (const float*)d_in[20];
    const float* bs2 = (const float*)d_in[21];
    const float* Ws3 = (const float*)d_in[22];
    const float* bs3 = (const float*)d_in[23];
    float* outp = (float*)d_out;

    float *dist, *xx, *xcat, *base, *wc, *act, *gvec, *sterm, *h1, *h2;
    int* idxp;
    cudaGetSymbolAddress((void**)&dist,  g_dist);
    cudaGetSymbolAddress((void**)&idxp,  g_idx);
    cudaGetSymbolAddress((void**)&xx,    g_xx);
    cudaGetSymbolAddress((void**)&xcat,  g_xcat);
    cudaGetSymbolAddress((void**)&base,  g_base);
    cudaGetSymbolAddress((void**)&wc,    g_Wc);
    cudaGetSymbolAddress((void**)&act,   g_act);
    cudaGetSymbolAddress((void**)&gvec,  g_gvec);
    cudaGetSymbolAddress((void**)&sterm, g_sterm);
    cudaGetSymbolAddress((void**)&h1,    g_h1);
    cudaGetSymbolAddress((void**)&h2,    g_h2);

    // Layer 1 (kNN on raw xyz, C=3, O=64 -> xcat[:, 0:64])
    k_sqnorm<<<NB / 256, 256>>>(x, 3, 3, xx);
    k_dist<<<dim3(NPT / 128, NPT / 128, BATCH), 256>>>(x, 3, 3, xx, dist);
    k_topk<<<NB / 8, 256>>>(dist, idxp);
    k_edge1<<<NB, 64>>>(x, idxp, W1, s1, b1, xcat);

    // Layers 2-4
    edge_layer(xcat, 0,   64,  W2, s2, b2, 64,  64,  xx, dist, idxp, wc, base);
    edge_layer(xcat, 64,  64,  W3, s3, b3, 128, 128, xx, dist, idxp, wc, base);
    edge_layer(xcat, 128, 128, W4, s4, b4, 256, 256, xx, dist, idxp, wc, base);

    // Global feature: g = max_n lrelu(sg*(xcat.Wg^T)+bg)
    k_gemm<128><<<dim3(NB / 128, 1024 / 128), 256>>>(xcat, 512, Wg, 512, 512, 1024,
                                                     sg, bg, nullptr, act, 1024, 1);
    k_rowmax<<<dim3(4, BATCH), 256>>>(act, gvec);

    // Ws1: split [xcat ; g] -> GEMM on xcat + per-batch sterm from g
    k_sterm<<<4, 256>>>(Ws1, gvec, sterm);
    k_gemm<128><<<dim3(NB / 128, 512 / 128), 256>>>(xcat, 512, Ws1, 1536, 512, 512,
                                                    ss1, bs1, sterm, h1, 512, 1);
    // Ws2
    k_gemm<128><<<dim3(NB / 128, 256 / 128), 256>>>(h1, 512, Ws2, 512, 512, 256,
                                                    ss2, bs2, nullptr, h2, 256, 1);
    // Ws3 (13 classes) + bias
    k_out<<<NB / 256, 256>>>(h2, Ws3, bs3, outp);
}